// round 13
// baseline (speedup 1.0000x reference)
#include <cuda_runtime.h>
#include <cuda_bf16.h>
#include <cstdint>

typedef unsigned long long u64;
typedef unsigned int u32;
typedef __nv_bfloat16 bf16;

constexpr int N_ELEC = 8192;
constexpr int DIM    = 256;
constexpr int NNB    = 24;
constexpr int F0     = 32;
constexpr int F1     = 16;
constexpr int NENV   = 8;
constexpr float CUTOFF = 5.0f;

// ---------------- scratch (device globals; no allocation) ----------------
__device__ float g_e1  [N_ELEC * DIM];
__device__ float g_hmsg[N_ELEC * DIM];
__device__ bf16 g_eh [N_ELEC * DIM], g_el [N_ELEC * DIM];
__device__ bf16 g_e1h[N_ELEC * DIM], g_e1l[N_ELEC * DIM];
__device__ bf16 g_t1h[N_ELEC * DIM], g_t1l[N_ELEC * DIM];
__device__ bf16 g_t2h[N_ELEC * DIM], g_t2l[N_ELEC * DIM];
__device__ bf16 g_w0h[DIM * DIM], g_w0l[DIM * DIM];
__device__ bf16 g_w1h[DIM * DIM], g_w1l[DIM * DIM];
__device__ bf16 g_w2h[DIM * DIM], g_w2l[DIM * DIM];
__device__ bf16 g_w3h[DIM * DIM], g_w3l[DIM * DIM];

// ---------------- helpers ----------------
__device__ __forceinline__ u64 pk2(float x, float y) {
    u64 r; asm("mov.b64 %0, {%1,%2};" : "=l"(r) : "f"(x), "f"(y)); return r;
}
__device__ __forceinline__ float2 upk2(u64 v) {
    float2 f; asm("mov.b64 {%0,%1}, %2;" : "=f"(f.x), "=f"(f.y) : "l"(v)); return f;
}
__device__ __forceinline__ u64 f2fma(u64 a, u64 b, u64 c) {
    u64 d; asm("fma.rn.f32x2 %0, %1, %2, %3;" : "=l"(d) : "l"(a), "l"(b), "l"(c));
    return d;
}
__device__ __forceinline__ float silu_f(float x) {
    float e = __expf(-x);
    return __fdividef(x, 1.0f + e);
}

__device__ __forceinline__ void mma_bf16(
    float c[4], u32 a0, u32 a1, u32 a2, u32 a3, u32 b0, u32 b1)
{
    asm volatile(
        "mma.sync.aligned.m16n8k16.row.col.f32.bf16.bf16.f32 "
        "{%0,%1,%2,%3}, {%4,%5,%6,%7}, {%8,%9}, {%0,%1,%2,%3};"
        : "+f"(c[0]), "+f"(c[1]), "+f"(c[2]), "+f"(c[3])
        : "r"(a0), "r"(a1), "r"(a2), "r"(a3), "r"(b0), "r"(b1));
}

__device__ __forceinline__ void ldm_x4(u32 r[4], u32 addr) {
    asm volatile(
        "ldmatrix.sync.aligned.m8n8.x4.shared.b16 {%0,%1,%2,%3}, [%4];"
        : "=r"(r[0]), "=r"(r[1]), "=r"(r[2]), "=r"(r[3]) : "r"(addr));
}

__device__ __forceinline__ void cp16(u32 dst, const void* src) {
    asm volatile("cp.async.cg.shared.global [%0], [%1], 16;"
                 :: "r"(dst), "l"(src));
}
#define CP_COMMIT() asm volatile("cp.async.commit_group;" ::: "memory")
#define CP_WAIT(n)  asm volatile("cp.async.wait_group %0;" :: "n"(n) : "memory")

// ---------------- prep kernels ----------------
__global__ __launch_bounds__(256) void split_f32(
    const float* __restrict__ x, bf16* __restrict__ h,
    bf16* __restrict__ l, int n4)
{
    int i = blockIdx.x * 256 + threadIdx.x;
    if (i >= n4) return;
    float4 v = ((const float4*)x)[i];
    float vv[4] = { v.x, v.y, v.z, v.w };
    bf16 hh[4], ll[4];
#pragma unroll
    for (int j = 0; j < 4; j++) {
        hh[j] = __float2bfloat16(vv[j]);
        ll[j] = __float2bfloat16(vv[j] - __bfloat162float(hh[j]));
    }
    ((uint2*)h)[i] = *(uint2*)hh;
    ((uint2*)l)[i] = *(uint2*)ll;
}

__global__ __launch_bounds__(256) void split_weights(
    const float* __restrict__ W0, const float* __restrict__ W1,
    const float* __restrict__ W2, const float* __restrict__ W3,
    bf16* __restrict__ o0h, bf16* __restrict__ o0l,
    bf16* __restrict__ o1h, bf16* __restrict__ o1l,
    bf16* __restrict__ o2h, bf16* __restrict__ o2l,
    bf16* __restrict__ o3h, bf16* __restrict__ o3l)
{
    __shared__ float t[32][33];
    const int z = blockIdx.z;
    const float* W = (z == 0) ? W0 : (z == 1) ? W1 : (z == 2) ? W2 : W3;
    bf16* oh = (z == 0) ? o0h : (z == 1) ? o1h : (z == 2) ? o2h : o3h;
    bf16* ol = (z == 0) ? o0l : (z == 1) ? o1l : (z == 2) ? o2l : o3l;

    const int tx = threadIdx.x;
    const int ty = threadIdx.y;
    const int jb = blockIdx.x * 32;
    const int kb = blockIdx.y * 32;

#pragma unroll
    for (int i = 0; i < 4; i++)
        t[ty + i * 8][tx] = W[(size_t)(kb + ty + i * 8) * DIM + jb + tx];
    __syncthreads();

#pragma unroll
    for (int i = 0; i < 4; i++) {
        const float v = t[tx][ty + i * 8];
        const bf16 h = __float2bfloat16(v);
        const bf16 l = __float2bfloat16(v - __bfloat162float(h));
        const size_t o = (size_t)(jb + ty + i * 8) * DIM + kb + tx;
        oh[o] = h;
        ol[o] = l;
    }
}

// ---------------------------------------------------------------------------
// mma.sync GEMM: CTA 128x64, 8 warps (4m x 2n), warp tile 32x32.
// K chunks of 64, double-buffered via cp.async. D = Ah@Bh + Ah@Bl + Al@Bh.
// MODE 0: f32 + hi/lo out    MODE 1: hi/lo out (+extra)    MODE 2: f32 out
// ---------------------------------------------------------------------------
constexpr int LDT   = 72;
constexpr int ARR_A = 128 * LDT;           // 9216 elems
constexpr int ARR_B = 64 * LDT;            // 4608 elems
constexpr int BUF   = 2 * ARR_A + 2 * ARR_B;   // 27648 elems
constexpr int GSMEM = 2 * BUF * 2;         // 110592 bytes

template <int MODE>
__global__ __launch_bounds__(256) void gemm_mma(
    const bf16* __restrict__ Ah, const bf16* __restrict__ Al,
    const bf16* __restrict__ BTh, const bf16* __restrict__ BTl,
    const float* __restrict__ bias, const float* __restrict__ extra,
    const float* __restrict__ res, const float* __restrict__ scale_p,
    float* __restrict__ out_f32,
    bf16* __restrict__ out_h, bf16* __restrict__ out_l)
{
    extern __shared__ bf16 sm[];
    const u32 smb = (u32)__cvta_generic_to_shared(sm);

    const int tid  = threadIdx.x;
    const int wid  = tid >> 5;
    const int lane = tid & 31;
    const int wm   = wid & 3;        // 4 warp rows of 32 m
    const int wn   = wid >> 2;       // 2 warp cols of 32 n
    const int m0   = blockIdx.y * 128;
    const int n0   = blockIdx.x * 64;

    const int lr = lane >> 2;
    const int lc = (lane & 3) * 2;

    // staging: slot s -> row = s>>3, vec = s&7 (8 bf16)
    const int srow = tid >> 3, svec = tid & 7;
    const u32 soff = (u32)(srow * LDT + svec * 8) * 2;   // byte offset of slot tid
    const u32 sstep = (u32)(32 * LDT) * 2;               // +256 slots = +32 rows

    float acc[2][4][4];
#pragma unroll
    for (int i = 0; i < 2; i++)
#pragma unroll
        for (int j = 0; j < 4; j++)
#pragma unroll
            for (int q = 0; q < 4; q++) acc[i][j][q] = 0.0f;

    // ldmatrix lane addressing
    const int a_row = wm * 32 + ((lane >> 3) & 1) * 8 + (lane & 7);
    const int a_kof = (lane >> 4) << 3;
    const int b_row = wn * 32 + ((lane >> 4) << 3) + (lane & 7);
    const int b_kof = ((lane >> 3) & 1) << 3;

    auto issue_chunk = [&](int c, int buf) {
        const int k0 = c * 64;
        const u32 ah_b = smb + (buf * BUF) * 2;
        const u32 al_b = ah_b + ARR_A * 2;
        const u32 bh_b = ah_b + 2 * ARR_A * 2;
        const u32 bl_b = bh_b + ARR_B * 2;
        // A: 4 slots per array
#pragma unroll
        for (int i = 0; i < 4; i++) {
            const size_t g = (size_t)(m0 + srow + i * 32) * DIM + k0 + svec * 8;
            cp16(ah_b + soff + i * sstep, Ah + g);
            cp16(al_b + soff + i * sstep, Al + g);
        }
        // B: 2 slots per array
#pragma unroll
        for (int i = 0; i < 2; i++) {
            const size_t g = (size_t)(n0 + srow + i * 32) * DIM + k0 + svec * 8;
            cp16(bh_b + soff + i * sstep, BTh + g);
            cp16(bl_b + soff + i * sstep, BTl + g);
        }
        CP_COMMIT();
    };

    auto compute_chunk = [&](int buf) {
        const u32 ah_b = smb + (buf * BUF) * 2;
        const u32 al_b = ah_b + ARR_A * 2;
        const u32 bh_b = ah_b + 2 * ARR_A * 2;
        const u32 bl_b = bh_b + ARR_B * 2;
#pragma unroll
        for (int ks = 0; ks < 4; ks++) {
            const int kb = ks * 16;
            u32 ah[2][4], al[2][4], bh[8], bl[8];
#pragma unroll
            for (int mt = 0; mt < 2; mt++) {
                const u32 aoff = (u32)((a_row + mt * 16) * LDT + kb + a_kof) * 2;
                ldm_x4(ah[mt], ah_b + aoff);
                ldm_x4(al[mt], al_b + aoff);
            }
#pragma unroll
            for (int g = 0; g < 2; g++) {
                const u32 boff = (u32)((b_row + g * 16) * LDT + kb + b_kof) * 2;
                ldm_x4(bh + g * 4, bh_b + boff);
                ldm_x4(bl + g * 4, bl_b + boff);
            }
#pragma unroll
            for (int mt = 0; mt < 2; mt++)
#pragma unroll
                for (int nt = 0; nt < 4; nt++) {
                    mma_bf16(acc[mt][nt], ah[mt][0], ah[mt][1], ah[mt][2], ah[mt][3],
                             bh[nt * 2], bh[nt * 2 + 1]);
                    mma_bf16(acc[mt][nt], ah[mt][0], ah[mt][1], ah[mt][2], ah[mt][3],
                             bl[nt * 2], bl[nt * 2 + 1]);
                    mma_bf16(acc[mt][nt], al[mt][0], al[mt][1], al[mt][2], al[mt][3],
                             bh[nt * 2], bh[nt * 2 + 1]);
                }
        }
    };

    issue_chunk(0, 0);
    for (int c = 0; c < 4; c++) {
        const int buf = c & 1;
        if (c < 3) {
            issue_chunk(c + 1, buf ^ 1);
            CP_WAIT(1);
        } else {
            CP_WAIT(0);
        }
        __syncthreads();
        compute_chunk(buf);
        __syncthreads();
    }

    // ---- epilogue ----
    float sc = 1.0f;
    if (MODE == 2) sc = *scale_p;

#pragma unroll
    for (int mt = 0; mt < 2; mt++)
#pragma unroll
        for (int nt = 0; nt < 4; nt++) {
            const int col = n0 + wn * 32 + nt * 8 + lc;
            const float2 bv = *(const float2*)(bias + col);
#pragma unroll
            for (int half = 0; half < 2; half++) {
                const int row = m0 + wm * 32 + mt * 16 + lr + half * 8;
                const size_t off = (size_t)row * DIM + col;
                float w0 = acc[mt][nt][2 * half + 0] + bv.x;
                float w1 = acc[mt][nt][2 * half + 1] + bv.y;
                if (MODE == 1) {
                    float2 e = *(const float2*)(extra + off);
                    w0 += e.x; w1 += e.y;
                }
                float o0 = silu_f(w0), o1 = silu_f(w1);
                if (MODE == 2) {
                    float2 rv = *(const float2*)(res + off);
                    o0 = (o0 + rv.x) * sc;
                    o1 = (o1 + rv.y) * sc;
                }
                if (MODE != 1)
                    *(float2*)(out_f32 + off) = make_float2(o0, o1);
                if (MODE != 2) {
                    bf16 h0 = __float2bfloat16(o0);
                    bf16 h1 = __float2bfloat16(o1);
                    bf16 l0 = __float2bfloat16(o0 - __bfloat162float(h0));
                    bf16 l1 = __float2bfloat16(o1 - __bfloat162float(h1));
                    bf16 hp[2] = { h0, h1 }, lp[2] = { l0, l1 };
                    *(u32*)(out_h + off) = *(u32*)hp;
                    *(u32*)(out_l + off) = *(u32*)lp;
                }
            }
        }
}

// ---------------------------------------------------------------------------
// Pair kernel — R9 VERBATIM (frozen; do not modify).
// ---------------------------------------------------------------------------
constexpr int NPB   = 4;
constexpr int PAIRS = NPB * NNB;   // 96

__global__ __launch_bounds__(256) void pair_kernel(
    const float* __restrict__ elec1,
    const float* __restrict__ r,
    const float* __restrict__ r_nb,
    const int*   __restrict__ s,
    const int*   __restrict__ s_nb,
    const float* __restrict__ hinit_nb,
    const float* __restrict__ ee_scales,
    const float* __restrict__ ee_kernel,
    const float* __restrict__ ee_bias,
    const float* __restrict__ Wf,
    const float* __restrict__ bf,
    const float* __restrict__ Wsame,
    const float* __restrict__ Wdiff,
    float* __restrict__ hinit_msg)
{
    __shared__ __align__(16) float beta_s[PAIRS][F1];
    __shared__ float maskf_s[PAIRS];
    __shared__ u64  wd2_s [8][DIM];
    __shared__ u64  wsd2_s[8][DIM];
    __shared__ float eek_s[4 * F0];
    __shared__ float eeb_s[F0];
    __shared__ float wf_s[(F0 + NENV) * F1];
    __shared__ float bfv_s[F1];
    __shared__ float scl_s[NENV];

    const int tid = threadIdx.x;
    const int n0  = blockIdx.x * NPB;

    for (int i = tid; i < 4 * F0; i += 256) eek_s[i] = ee_kernel[i];
    for (int i = tid; i < F0; i += 256)     eeb_s[i] = ee_bias[i];
    for (int i = tid; i < (F0 + NENV) * F1; i += 256) wf_s[i] = Wf[i];
    if (tid < F1)   bfv_s[tid] = bf[tid];
    if (tid < NENV) scl_s[tid] = ee_scales[tid];

#pragma unroll
    for (int i = 0; i < 8; i++) {
        float d0 = Wdiff[(2 * i + 0) * DIM + tid];
        float d1 = Wdiff[(2 * i + 1) * DIM + tid];
        float s0 = Wsame[(2 * i + 0) * DIM + tid] - d0;
        float s1 = Wsame[(2 * i + 1) * DIM + tid] - d1;
        wd2_s [i][tid] = pk2(d0, d1);
        wsd2_s[i][tid] = pk2(s0, s1);
    }
    __syncthreads();

    if (tid < PAIRS) {
        const int nl = tid / NNB;
        const int k  = tid % NNB;
        const int n  = n0 + nl;

        const float rx = r[n * 3 + 0];
        const float ry = r[n * 3 + 1];
        const float rz = r[n * 3 + 2];
        const float* rn = r_nb + (size_t)(n * NNB + k) * 3;
        const float dx = rn[0] - rx;
        const float dy = rn[1] - ry;
        const float dz = rn[2] - rz;
        const float dist = sqrtf(dx * dx + dy * dy + dz * dz + 1e-12f);

        float feats[4] = { dist, dx, dy, dz };
        float h[F0];
#pragma unroll
        for (int j = 0; j < F0; j++) {
            float t = eeb_s[j];
#pragma unroll
            for (int f = 0; f < 4; f++) t += feats[f] * eek_s[f * F0 + j];
            h[j] = silu_f(t);
        }
        float env[NENV];
#pragma unroll
        for (int e = 0; e < NENV; e++) {
            float q = __fdividef(dist, scl_s[e]);
            env[e] = __expf(-q * q);
        }
        const float xx  = dist * (1.0f / CUTOFF);
        const float cut = (dist < CUTOFF)
                        ? (1.0f - xx) * (1.0f - xx) * (1.0f + 2.0f * xx)
                        : 0.0f;
#pragma unroll
        for (int i = 0; i < F1; i++) {
            float b = bfv_s[i];
#pragma unroll
            for (int j = 0; j < F0; j++)   b += h[j]   * wf_s[j * F1 + i];
#pragma unroll
            for (int e = 0; e < NENV; e++) b += env[e] * wf_s[(F0 + e) * F1 + i];
            beta_s[tid][i] = b * cut;
        }
        maskf_s[tid] = (s[n] == s_nb[n * NNB + k]) ? 1.0f : 0.0f;
    }
    __syncthreads();

    const int d = tid;
#pragma unroll
    for (int nl = 0; nl < NPB; nl++) {
        const int n = n0 + nl;
        const float e1 = elec1[(size_t)n * DIM + d];
        const float* hb = hinit_nb + ((size_t)n * NNB) * DIM + d;

        u64 vall[8], vsm[8];
#pragma unroll
        for (int i = 0; i < 8; i++) { vall[i] = 0ull; vsm[i] = 0ull; }

#pragma unroll
        for (int g = 0; g < 3; g++) {
            float uu[8];
#pragma unroll
            for (int kk = 0; kk < 8; kk++)
                uu[kk] = e1 + hb[(size_t)(g * 8 + kk) * DIM];
#pragma unroll
            for (int kk = 0; kk < 8; kk++)
                uu[kk] = silu_f(uu[kk]);
#pragma unroll
            for (int kk = 0; kk < 8; kk++) {
                const int pair = nl * NNB + g * 8 + kk;
                const float u  = uu[kk];
                const float um = u * maskf_s[pair];
                const u64 u2   = pk2(u, u);
                const u64 um2  = pk2(um, um);
                const u64* bp  = (const u64*)beta_s[pair];
#pragma unroll
                for (int i = 0; i < 8; i++) {
                    vall[i] = f2fma(u2,  bp[i], vall[i]);
                    vsm[i]  = f2fma(um2, bp[i], vsm[i]);
                }
            }
        }

        u64 r2 = 0ull;
#pragma unroll
        for (int i = 0; i < 8; i++) r2 = f2fma(wd2_s[i][d],  vall[i], r2);
#pragma unroll
        for (int i = 0; i < 8; i++) r2 = f2fma(wsd2_s[i][d], vsm[i],  r2);
        float2 rr = upk2(r2);
        hinit_msg[(size_t)n * DIM + d] = rr.x + rr.y;
    }
}

// ---------------------------------------------------------------------------
extern "C" void kernel_launch(void* const* d_in, const int* in_sizes, int n_in,
                              void* d_out, int out_size)
{
    const float* elec     = (const float*)d_in[0];
    const float* msg      = (const float*)d_in[1];
    const float* r        = (const float*)d_in[2];
    const float* r_nb     = (const float*)d_in[3];
    const int*   s        = (const int*)  d_in[4];
    const int*   s_nb     = (const int*)  d_in[5];
    const float* hinit_nb = (const float*)d_in[6];
    const float* W_in     = (const float*)d_in[7];
    const float* b_in     = (const float*)d_in[8];
    const float* ee_scales= (const float*)d_in[9];
    const float* ee_kernel= (const float*)d_in[10];
    const float* ee_bias  = (const float*)d_in[11];
    const float* Wf       = (const float*)d_in[12];
    const float* bf       = (const float*)d_in[13];
    const float* Wsame    = (const float*)d_in[14];
    const float* Wdiff    = (const float*)d_in[15];
    const float* W1       = (const float*)d_in[16];
    const float* b1       = (const float*)d_in[17];
    const float* W2       = (const float*)d_in[18];
    const float* b2       = (const float*)d_in[19];
    const float* W3       = (const float*)d_in[20];
    const float* b3       = (const float*)d_in[21];
    const float* scale    = (const float*)d_in[22];

    float* out = (float*)d_out;

    float *e1, *hmsg;
    bf16 *eh, *el, *e1h, *e1l, *t1h, *t1l, *t2h, *t2l;
    bf16 *w0h, *w0l, *w1h, *w1l, *w2h, *w2l, *w3h, *w3l;
    cudaGetSymbolAddress((void**)&e1,   g_e1);
    cudaGetSymbolAddress((void**)&hmsg, g_hmsg);
    cudaGetSymbolAddress((void**)&eh,  g_eh);  cudaGetSymbolAddress((void**)&el,  g_el);
    cudaGetSymbolAddress((void**)&e1h, g_e1h); cudaGetSymbolAddress((void**)&e1l, g_e1l);
    cudaGetSymbolAddress((void**)&t1h, g_t1h); cudaGetSymbolAddress((void**)&t1l, g_t1l);
    cudaGetSymbolAddress((void**)&t2h, g_t2h); cudaGetSymbolAddress((void**)&t2l, g_t2l);
    cudaGetSymbolAddress((void**)&w0h, g_w0h); cudaGetSymbolAddress((void**)&w0l, g_w0l);
    cudaGetSymbolAddress((void**)&w1h, g_w1h); cudaGetSymbolAddress((void**)&w1l, g_w1l);
    cudaGetSymbolAddress((void**)&w2h, g_w2h); cudaGetSymbolAddress((void**)&w2l, g_w2l);
    cudaGetSymbolAddress((void**)&w3h, g_w3h); cudaGetSymbolAddress((void**)&w3l, g_w3l);

    cudaFuncSetAttribute(gemm_mma<0>, cudaFuncAttributeMaxDynamicSharedMemorySize, GSMEM);
    cudaFuncSetAttribute(gemm_mma<1>, cudaFuncAttributeMaxDynamicSharedMemorySize, GSMEM);
    cudaFuncSetAttribute(gemm_mma<2>, cudaFuncAttributeMaxDynamicSharedMemorySize, GSMEM);

    // prep
    split_f32<<<(N_ELEC * DIM / 4 + 255) / 256, 256>>>(elec, eh, el, N_ELEC * DIM / 4);
    split_weights<<<dim3(8, 8, 4), dim3(32, 8)>>>(
        W_in, W1, W2, W3, w0h, w0l, w1h, w1l, w2h, w2l, w3h, w3l);

    dim3 ggrid(DIM / 64, N_ELEC / 128);   // (4, 64) = 256 CTAs

    gemm_mma<0><<<ggrid, 256, GSMEM>>>(eh, el, w0h, w0l, b_in,
                                       nullptr, nullptr, nullptr, e1, e1h, e1l);

    pair_kernel<<<N_ELEC / NPB, 256>>>(e1, r, r_nb, s, s_nb, hinit_nb,
                                       ee_scales, ee_kernel, ee_bias, Wf, bf,
                                       Wsame, Wdiff, hmsg);

    gemm_mma<1><<<ggrid, 256, GSMEM>>>(e1h, e1l, w1h, w1l, b1,
                                       hmsg, nullptr, nullptr, nullptr, t1h, t1l);
    gemm_mma<1><<<ggrid, 256, GSMEM>>>(t1h, t1l, w2h, w2l, b2,
                                       msg, nullptr, nullptr, nullptr, t2h, t2l);
    gemm_mma<2><<<ggrid, 256, GSMEM>>>(t2h, t2l, w3h, w3l, b3,
                                       nullptr, e1, scale, out, nullptr, nullptr);
}